// round 13
// baseline (speedup 1.0000x reference)
#include <cuda_runtime.h>
#include <cuda_bf16.h>
#include <cstdint>

#define D 64
#define MAXN 100000
#define MAXE 1200000
#define NEG_SLOPE 0.2f
#define SCAN_BLK 1024
#define MAX_SCAN_BLOCKS 128
#define HIST_BLOCKS 1024

// ---------------- scratch (static device globals; no allocation) ----------------
__device__ float g_z[MAXN * D];       // z = xW^T + b
__device__ float g_wt[D * D];         // W transposed
__device__ int   g_cnt[MAXN];         // in-degree histogram
__device__ int   g_off[MAXN + 1];     // CSR offsets
__device__ int   g_cur[MAXN];         // scatter cursors
__device__ int   g_csr[MAXE];         // src ids grouped by dst
__device__ int   g_bsum[MAX_SCAN_BLOCKS];

// ---------------- prep: zero histogram + transpose W ----------------
__global__ void prep_kernel(const float* __restrict__ W, int N) {
    int i = blockIdx.x * blockDim.x + threadIdx.x;
    if (i < N) g_cnt[i] = 0;
    if (i < D * D) {
        int j = i >> 6, k = i & 63;
        g_wt[k * D + j] = W[i];
    }
}

// ---------------- fused: z = xW^T + b (tile blocks)  +  dst histogram (tail blocks) ----------------
__global__ __launch_bounds__(256) void gemm_hist_kernel(const float* __restrict__ x,
                                                        const float* __restrict__ b,
                                                        const int* __restrict__ ei,
                                                        int N, int E, int gemmBlocks) {
    __shared__ float Ws[D * D];
    __shared__ float Xs[64 * D];

    int tid = threadIdx.x;

    if (blockIdx.x >= gemmBlocks) {
        // -------- histogram path (grid-stride) --------
        int e0 = (blockIdx.x - gemmBlocks) * 256 + tid;
        for (int e = e0; e < E; e += HIST_BLOCKS * 256)
            atomicAdd(&g_cnt[__ldg(ei + E + e)], 1);
        return;
    }

    // -------- GEMM path --------
    int row0 = blockIdx.x * 64;

    #pragma unroll
    for (int p = tid; p < D * D; p += 256) Ws[p] = g_wt[p];
    #pragma unroll
    for (int p = tid; p < 64 * D; p += 256) {
        int r = p >> 6, k = p & 63;
        int gr = row0 + r;
        Xs[p] = (gr < N) ? x[gr * D + k] : 0.0f;
    }
    __syncthreads();

    int tx = tid & 15;
    int ty = tid >> 4;

    float acc[4][4];
    #pragma unroll
    for (int r = 0; r < 4; r++)
        #pragma unroll
        for (int c = 0; c < 4; c++) acc[r][c] = 0.0f;

    #pragma unroll 8
    for (int k = 0; k < D; k++) {
        float4 w = *(const float4*)&Ws[k * D + tx * 4];
        #pragma unroll
        for (int r = 0; r < 4; r++) {
            float xv = Xs[(ty * 4 + r) * D + k];
            acc[r][0] = fmaf(xv, w.x, acc[r][0]);
            acc[r][1] = fmaf(xv, w.y, acc[r][1]);
            acc[r][2] = fmaf(xv, w.z, acc[r][2]);
            acc[r][3] = fmaf(xv, w.w, acc[r][3]);
        }
    }

    float4 bb = __ldg((const float4*)b + tx);
    #pragma unroll
    for (int r = 0; r < 4; r++) {
        int gr = row0 + ty * 4 + r;
        if (gr < N) {
            float4 o = make_float4(acc[r][0] + bb.x, acc[r][1] + bb.y,
                                   acc[r][2] + bb.z, acc[r][3] + bb.w);
            *(float4*)&g_z[gr * D + tx * 4] = o;
        }
    }
}

// ---------------- scan phase 1: per-block scan via shfl (1024 elems/block) ----------------
__global__ __launch_bounds__(256) void scan1_kernel(int N) {
    __shared__ int wsum[8];
    int t = threadIdx.x;
    int blk = blockIdx.x;
    int wid = t >> 5, ln = t & 31;
    int i0 = blk * SCAN_BLK + t * 4;

    int c[4];
    #pragma unroll
    for (int j = 0; j < 4; j++) c[j] = (i0 + j < N) ? g_cnt[i0 + j] : 0;
    int tsum = c[0] + c[1] + c[2] + c[3];

    // warp-inclusive scan of tsum
    int v = tsum;
    #pragma unroll
    for (int off = 1; off < 32; off <<= 1) {
        int u = __shfl_up_sync(0xffffffffu, v, off);
        if (ln >= off) v += u;
    }
    if (ln == 31) wsum[wid] = v;
    __syncthreads();
    if (wid == 0) {
        int w = (ln < 8) ? wsum[ln] : 0;
        #pragma unroll
        for (int off = 1; off < 8; off <<= 1) {
            int u = __shfl_up_sync(0xffffffffu, w, off);
            if (ln >= off) w += u;
        }
        if (ln < 8) wsum[ln] = w;
    }
    __syncthreads();
    int base = (wid > 0) ? wsum[wid - 1] : 0;
    int excl = base + v - tsum;

    int run = excl;
    #pragma unroll
    for (int j = 0; j < 4; j++) {
        run += c[j];
        if (i0 + j < N) g_off[i0 + j + 1] = run;
    }
    if (t == 255) g_bsum[blk] = base + v;   // block total
    if (blk == 0 && t == 0) g_off[0] = 0;
}

// ---------------- scan phase 2: redundant block-sum scan + fixup + cursors ----------------
__global__ __launch_bounds__(256) void scan2_kernel(int N, int nb) {
    __shared__ int sb[128];
    int t = threadIdx.x;
    if (t < 128) sb[t] = (t < nb) ? g_bsum[t] : 0;
    __syncthreads();
    #pragma unroll
    for (int off = 1; off < 128; off <<= 1) {
        int v = (t < 128 && t >= off) ? sb[t - off] : 0;
        __syncthreads();
        if (t < 128) sb[t] += v;
        __syncthreads();
    }
    int i = blockIdx.x * 256 + t;
    if (i < N) {
        int blk = i >> 10;
        int base = (blk > 0) ? sb[blk - 1] : 0;
        int fin = g_off[i + 1] + base;
        g_off[i + 1] = fin;
        g_cur[i] = fin - g_cnt[i];
    }
}

// ---------------- scatter edges into CSR by dst ----------------
__global__ __launch_bounds__(256) void scatter_kernel(const int* __restrict__ ei, int E) {
    int e = blockIdx.x * blockDim.x + threadIdx.x;
    if (e >= E) return;
    int src = __ldg(ei + e);
    int dst = __ldg(ei + E + e);
    int p = atomicAdd(&g_cur[dst], 1);
    g_csr[p] = src;
}

// ---------------- FUSED aggregate: one warp per dst, 8 lanes/edge, 4 edges/iter ----------------
// Lane layout: q = lane>>3 selects one of 4 concurrent edges, sub = lane&7 selects
// feature float4s {sub, sub+8} (each load instruction covers one 128B sector).
// 3 shfls reduce the 8-lane dot, shared by all 4 edges. Accumulator + z_dst in regs.
__global__ __launch_bounds__(256) void aggregate_kernel(const float* __restrict__ x,
                                                        const float* __restrict__ att,
                                                        float* __restrict__ out,
                                                        int N) {
    int dst = blockIdx.x * 8 + (threadIdx.x >> 5);
    if (dst >= N) return;
    int lane = threadIdx.x & 31;
    int q   = lane >> 3;
    int sub = lane & 7;

    const float4* zrd = (const float4*)(g_z + (dst << 6));
    float4 zd0 = zrd[sub], zd1 = zrd[sub + 8];
    float4 a0 = __ldg((const float4*)att + sub);
    float4 a1 = __ldg((const float4*)att + sub + 8);

    int beg = __ldg(&g_off[dst]);
    int end = __ldg(&g_off[dst + 1]);

    float4 acc0 = make_float4(0.f, 0.f, 0.f, 0.f);
    float4 acc1 = make_float4(0.f, 0.f, 0.f, 0.f);
    float s = 0.f;

    for (int k4 = beg; k4 < end; k4 += 4) {
        int k = k4 + q;
        bool valid = (k < end);
        int src = valid ? __ldg(&g_csr[k]) : 0;

        const float4* zr = (const float4*)(g_z + (src << 6));
        float4 z0 = zr[sub], z1 = zr[sub + 8];

        float u, pv = 0.f;
        u = z0.x + zd0.x; u = (u > 0.f) ? u : NEG_SLOPE * u; pv = fmaf(a0.x, u, pv);
        u = z0.y + zd0.y; u = (u > 0.f) ? u : NEG_SLOPE * u; pv = fmaf(a0.y, u, pv);
        u = z0.z + zd0.z; u = (u > 0.f) ? u : NEG_SLOPE * u; pv = fmaf(a0.z, u, pv);
        u = z0.w + zd0.w; u = (u > 0.f) ? u : NEG_SLOPE * u; pv = fmaf(a0.w, u, pv);
        u = z1.x + zd1.x; u = (u > 0.f) ? u : NEG_SLOPE * u; pv = fmaf(a1.x, u, pv);
        u = z1.y + zd1.y; u = (u > 0.f) ? u : NEG_SLOPE * u; pv = fmaf(a1.y, u, pv);
        u = z1.z + zd1.z; u = (u > 0.f) ? u : NEG_SLOPE * u; pv = fmaf(a1.z, u, pv);
        u = z1.w + zd1.w; u = (u > 0.f) ? u : NEG_SLOPE * u; pv = fmaf(a1.w, u, pv);

        // reduce within each 8-lane group (xor stays inside the group)
        #pragma unroll
        for (int off = 4; off > 0; off >>= 1)
            pv += __shfl_xor_sync(0xffffffffu, pv, off);

        float ex = valid ? __expf(pv) : 0.f;

        const float4* xr = (const float4*)(x + (src << 6));
        float4 x0 = __ldg(xr + sub), x1 = __ldg(xr + sub + 8);
        acc0.x = fmaf(ex, x0.x, acc0.x);
        acc0.y = fmaf(ex, x0.y, acc0.y);
        acc0.z = fmaf(ex, x0.z, acc0.z);
        acc0.w = fmaf(ex, x0.w, acc0.w);
        acc1.x = fmaf(ex, x1.x, acc1.x);
        acc1.y = fmaf(ex, x1.y, acc1.y);
        acc1.z = fmaf(ex, x1.z, acc1.z);
        acc1.w = fmaf(ex, x1.w, acc1.w);
        s += ex;
    }

    // combine the 4 quarters
    #pragma unroll
    for (int off = 8; off <= 16; off <<= 1) {
        acc0.x += __shfl_xor_sync(0xffffffffu, acc0.x, off);
        acc0.y += __shfl_xor_sync(0xffffffffu, acc0.y, off);
        acc0.z += __shfl_xor_sync(0xffffffffu, acc0.z, off);
        acc0.w += __shfl_xor_sync(0xffffffffu, acc0.w, off);
        acc1.x += __shfl_xor_sync(0xffffffffu, acc1.x, off);
        acc1.y += __shfl_xor_sync(0xffffffffu, acc1.y, off);
        acc1.z += __shfl_xor_sync(0xffffffffu, acc1.z, off);
        acc1.w += __shfl_xor_sync(0xffffffffu, acc1.w, off);
        s      += __shfl_xor_sync(0xffffffffu, s, off);
    }

    float inv = (s > 0.f) ? __frcp_rn(s) : 0.f;
    if (q == 0) {
        float4* o = (float4*)(out + (dst << 6));
        o[sub]     = make_float4(acc0.x * inv, acc0.y * inv, acc0.z * inv, acc0.w * inv);
        o[sub + 8] = make_float4(acc1.x * inv, acc1.y * inv, acc1.z * inv, acc1.w * inv);
    }
}

// ---------------- launch ----------------
extern "C" void kernel_launch(void* const* d_in, const int* in_sizes, int n_in,
                              void* d_out, int out_size) {
    const float* x   = (const float*)d_in[0];
    const int*   ei  = (const int*)d_in[1];
    const float* W   = (const float*)d_in[2];
    const float* b   = (const float*)d_in[3];
    const float* att = (const float*)d_in[4];
    float* out = (float*)d_out;

    int N = in_sizes[0] / D;
    int E = in_sizes[1] / 2;
    int nb = (N + SCAN_BLK - 1) / SCAN_BLK;
    int gemmBlocks = (N + 63) / 64;

    prep_kernel<<<(N + 255) / 256, 256>>>(W, N);
    gemm_hist_kernel<<<gemmBlocks + HIST_BLOCKS, 256>>>(x, b, ei, N, E, gemmBlocks);
    scan1_kernel<<<nb, 256>>>(N);
    scan2_kernel<<<(N + 255) / 256, 256>>>(N, nb);
    scatter_kernel<<<(E + 255) / 256, 256>>>(ei, E);
    aggregate_kernel<<<(N + 7) / 8, 256>>>(x, att, out, N);
}

// round 14
// speedup vs baseline: 1.0117x; 1.0117x over previous
#include <cuda_runtime.h>
#include <cuda_bf16.h>
#include <cstdint>

#define D 64
#define MAXN 100000
#define MAXE 1200000
#define NEG_SLOPE 0.2f
#define SCAN_BLK 1024
#define MAX_SCAN_BLOCKS 128
#define HIST_BLOCKS 1024

// ---------------- scratch (static device globals; no allocation) ----------------
__device__ float g_z[MAXN * D];       // z = xW^T + b
__device__ float g_wt[D * D];         // W transposed
__device__ int   g_cnt[MAXN];         // in-degree histogram
__device__ int   g_off[MAXN + 1];     // CSR offsets
__device__ int   g_cur[MAXN];         // scatter cursors
__device__ int   g_csr[MAXE];         // src ids grouped by dst
__device__ int   g_bsum[MAX_SCAN_BLOCKS];

// ---------------- prep: zero histogram + transpose W ----------------
__global__ void prep_kernel(const float* __restrict__ W, int N) {
    int i = blockIdx.x * blockDim.x + threadIdx.x;
    if (i < N) g_cnt[i] = 0;
    if (i < D * D) {
        int j = i >> 6, k = i & 63;
        g_wt[k * D + j] = W[i];
    }
}

// ---------------- fused: z = xW^T + b (tile blocks)  +  dst histogram (tail blocks) ----------------
__global__ __launch_bounds__(256) void gemm_hist_kernel(const float* __restrict__ x,
                                                        const float* __restrict__ b,
                                                        const int* __restrict__ ei,
                                                        int N, int E, int gemmBlocks) {
    __shared__ float Ws[D * D];
    __shared__ float Xs[64 * D];

    int tid = threadIdx.x;

    if (blockIdx.x >= gemmBlocks) {
        // -------- histogram path (grid-stride) --------
        int e0 = (blockIdx.x - gemmBlocks) * 256 + tid;
        for (int e = e0; e < E; e += HIST_BLOCKS * 256)
            atomicAdd(&g_cnt[__ldg(ei + E + e)], 1);
        return;
    }

    // -------- GEMM path --------
    int row0 = blockIdx.x * 64;

    #pragma unroll
    for (int p = tid; p < D * D; p += 256) Ws[p] = g_wt[p];
    #pragma unroll
    for (int p = tid; p < 64 * D; p += 256) {
        int r = p >> 6, k = p & 63;
        int gr = row0 + r;
        Xs[p] = (gr < N) ? x[gr * D + k] : 0.0f;
    }
    __syncthreads();

    int tx = tid & 15;
    int ty = tid >> 4;

    float acc[4][4];
    #pragma unroll
    for (int r = 0; r < 4; r++)
        #pragma unroll
        for (int c = 0; c < 4; c++) acc[r][c] = 0.0f;

    #pragma unroll 8
    for (int k = 0; k < D; k++) {
        float4 w = *(const float4*)&Ws[k * D + tx * 4];
        #pragma unroll
        for (int r = 0; r < 4; r++) {
            float xv = Xs[(ty * 4 + r) * D + k];
            acc[r][0] = fmaf(xv, w.x, acc[r][0]);
            acc[r][1] = fmaf(xv, w.y, acc[r][1]);
            acc[r][2] = fmaf(xv, w.z, acc[r][2]);
            acc[r][3] = fmaf(xv, w.w, acc[r][3]);
        }
    }

    float4 bb = __ldg((const float4*)b + tx);
    #pragma unroll
    for (int r = 0; r < 4; r++) {
        int gr = row0 + ty * 4 + r;
        if (gr < N) {
            float4 o = make_float4(acc[r][0] + bb.x, acc[r][1] + bb.y,
                                   acc[r][2] + bb.z, acc[r][3] + bb.w);
            *(float4*)&g_z[gr * D + tx * 4] = o;
        }
    }
}

// ---------------- scan phase 1: per-block scan via shfl (1024 elems/block) ----------------
__global__ __launch_bounds__(256) void scan1_kernel(int N) {
    __shared__ int wsum[8];
    int t = threadIdx.x;
    int blk = blockIdx.x;
    int wid = t >> 5, ln = t & 31;
    int i0 = blk * SCAN_BLK + t * 4;

    int c[4];
    #pragma unroll
    for (int j = 0; j < 4; j++) c[j] = (i0 + j < N) ? g_cnt[i0 + j] : 0;
    int tsum = c[0] + c[1] + c[2] + c[3];

    // warp-inclusive scan of tsum
    int v = tsum;
    #pragma unroll
    for (int off = 1; off < 32; off <<= 1) {
        int u = __shfl_up_sync(0xffffffffu, v, off);
        if (ln >= off) v += u;
    }
    if (ln == 31) wsum[wid] = v;
    __syncthreads();
    if (wid == 0) {
        int w = (ln < 8) ? wsum[ln] : 0;
        #pragma unroll
        for (int off = 1; off < 8; off <<= 1) {
            int u = __shfl_up_sync(0xffffffffu, w, off);
            if (ln >= off) w += u;
        }
        if (ln < 8) wsum[ln] = w;
    }
    __syncthreads();
    int base = (wid > 0) ? wsum[wid - 1] : 0;
    int excl = base + v - tsum;

    int run = excl;
    #pragma unroll
    for (int j = 0; j < 4; j++) {
        run += c[j];
        if (i0 + j < N) g_off[i0 + j + 1] = run;
    }
    if (t == 255) g_bsum[blk] = base + v;   // block total
    if (blk == 0 && t == 0) g_off[0] = 0;
}

// ---------------- scan phase 2: redundant block-sum scan + fixup + cursors ----------------
__global__ __launch_bounds__(256) void scan2_kernel(int N, int nb) {
    __shared__ int sb[128];
    int t = threadIdx.x;
    if (t < 128) sb[t] = (t < nb) ? g_bsum[t] : 0;
    __syncthreads();
    #pragma unroll
    for (int off = 1; off < 128; off <<= 1) {
        int v = (t < 128 && t >= off) ? sb[t - off] : 0;
        __syncthreads();
        if (t < 128) sb[t] += v;
        __syncthreads();
    }
    int i = blockIdx.x * 256 + t;
    if (i < N) {
        int blk = i >> 10;
        int base = (blk > 0) ? sb[blk - 1] : 0;
        int fin = g_off[i + 1] + base;
        g_off[i + 1] = fin;
        g_cur[i] = fin - g_cnt[i];
    }
}

// ---------------- scatter edges into CSR by dst ----------------
__global__ __launch_bounds__(256) void scatter_kernel(const int* __restrict__ ei, int E) {
    int e = blockIdx.x * blockDim.x + threadIdx.x;
    if (e >= E) return;
    int src = __ldg(ei + e);
    int dst = __ldg(ei + E + e);
    int p = atomicAdd(&g_cur[dst], 1);
    g_csr[p] = src;
}

// ---------------- FUSED aggregate: one warp per dst, 8 lanes/edge, 4 edges/iter ----------------
// Lane layout: q = lane>>3 selects one of 4 concurrent edges, sub = lane&7 selects
// feature float4s {sub, sub+8} (each load instruction covers one 128B sector).
// 3 shfls reduce the 8-lane dot, shared by all 4 edges. Accumulator + z_dst in regs.
__global__ __launch_bounds__(256) void aggregate_kernel(const float* __restrict__ x,
                                                        const float* __restrict__ att,
                                                        float* __restrict__ out,
                                                        int N) {
    int dst = blockIdx.x * 8 + (threadIdx.x >> 5);
    if (dst >= N) return;
    int lane = threadIdx.x & 31;
    int q   = lane >> 3;
    int sub = lane & 7;

    const float4* zrd = (const float4*)(g_z + (dst << 6));
    float4 zd0 = zrd[sub], zd1 = zrd[sub + 8];
    float4 a0 = __ldg((const float4*)att + sub);
    float4 a1 = __ldg((const float4*)att + sub + 8);

    int beg = __ldg(&g_off[dst]);
    int end = __ldg(&g_off[dst + 1]);

    float4 acc0 = make_float4(0.f, 0.f, 0.f, 0.f);
    float4 acc1 = make_float4(0.f, 0.f, 0.f, 0.f);
    float s = 0.f;

    for (int k4 = beg; k4 < end; k4 += 4) {
        int k = k4 + q;
        bool valid = (k < end);
        int src = valid ? __ldg(&g_csr[k]) : 0;

        const float4* zr = (const float4*)(g_z + (src << 6));
        float4 z0 = zr[sub], z1 = zr[sub + 8];

        float u, pv = 0.f;
        u = z0.x + zd0.x; u = (u > 0.f) ? u : NEG_SLOPE * u; pv = fmaf(a0.x, u, pv);
        u = z0.y + zd0.y; u = (u > 0.f) ? u : NEG_SLOPE * u; pv = fmaf(a0.y, u, pv);
        u = z0.z + zd0.z; u = (u > 0.f) ? u : NEG_SLOPE * u; pv = fmaf(a0.z, u, pv);
        u = z0.w + zd0.w; u = (u > 0.f) ? u : NEG_SLOPE * u; pv = fmaf(a0.w, u, pv);
        u = z1.x + zd1.x; u = (u > 0.f) ? u : NEG_SLOPE * u; pv = fmaf(a1.x, u, pv);
        u = z1.y + zd1.y; u = (u > 0.f) ? u : NEG_SLOPE * u; pv = fmaf(a1.y, u, pv);
        u = z1.z + zd1.z; u = (u > 0.f) ? u : NEG_SLOPE * u; pv = fmaf(a1.z, u, pv);
        u = z1.w + zd1.w; u = (u > 0.f) ? u : NEG_SLOPE * u; pv = fmaf(a1.w, u, pv);

        // reduce within each 8-lane group (xor stays inside the group)
        #pragma unroll
        for (int off = 4; off > 0; off >>= 1)
            pv += __shfl_xor_sync(0xffffffffu, pv, off);

        float ex = valid ? __expf(pv) : 0.f;

        const float4* xr = (const float4*)(x + (src << 6));
        float4 x0 = __ldg(xr + sub), x1 = __ldg(xr + sub + 8);
        acc0.x = fmaf(ex, x0.x, acc0.x);
        acc0.y = fmaf(ex, x0.y, acc0.y);
        acc0.z = fmaf(ex, x0.z, acc0.z);
        acc0.w = fmaf(ex, x0.w, acc0.w);
        acc1.x = fmaf(ex, x1.x, acc1.x);
        acc1.y = fmaf(ex, x1.y, acc1.y);
        acc1.z = fmaf(ex, x1.z, acc1.z);
        acc1.w = fmaf(ex, x1.w, acc1.w);
        s += ex;
    }

    // combine the 4 quarters
    #pragma unroll
    for (int off = 8; off <= 16; off <<= 1) {
        acc0.x += __shfl_xor_sync(0xffffffffu, acc0.x, off);
        acc0.y += __shfl_xor_sync(0xffffffffu, acc0.y, off);
        acc0.z += __shfl_xor_sync(0xffffffffu, acc0.z, off);
        acc0.w += __shfl_xor_sync(0xffffffffu, acc0.w, off);
        acc1.x += __shfl_xor_sync(0xffffffffu, acc1.x, off);
        acc1.y += __shfl_xor_sync(0xffffffffu, acc1.y, off);
        acc1.z += __shfl_xor_sync(0xffffffffu, acc1.z, off);
        acc1.w += __shfl_xor_sync(0xffffffffu, acc1.w, off);
        s      += __shfl_xor_sync(0xffffffffu, s, off);
    }

    float inv = (s > 0.f) ? __frcp_rn(s) : 0.f;
    if (q == 0) {
        float4* o = (float4*)(out + (dst << 6));
        o[sub]     = make_float4(acc0.x * inv, acc0.y * inv, acc0.z * inv, acc0.w * inv);
        o[sub + 8] = make_float4(acc1.x * inv, acc1.y * inv, acc1.z * inv, acc1.w * inv);
    }
}

// ---------------- launch ----------------
extern "C" void kernel_launch(void* const* d_in, const int* in_sizes, int n_in,
                              void* d_out, int out_size) {
    const float* x   = (const float*)d_in[0];
    const int*   ei  = (const int*)d_in[1];
    const float* W   = (const float*)d_in[2];
    const float* b   = (const float*)d_in[3];
    const float* att = (const float*)d_in[4];
    float* out = (float*)d_out;

    int N = in_sizes[0] / D;
    int E = in_sizes[1] / 2;
    int nb = (N + SCAN_BLK - 1) / SCAN_BLK;
    int gemmBlocks = (N + 63) / 64;

    prep_kernel<<<(N + 255) / 256, 256>>>(W, N);
    gemm_hist_kernel<<<gemmBlocks + HIST_BLOCKS, 256>>>(x, b, ei, N, E, gemmBlocks);
    scan1_kernel<<<nb, 256>>>(N);
    scan2_kernel<<<(N + 255) / 256, 256>>>(N, nb);
    scatter_kernel<<<(E + 255) / 256, 256>>>(ei, E);
    aggregate_kernel<<<(N + 7) / 8, 256>>>(x, att, out, N);
}

// round 15
// speedup vs baseline: 1.0287x; 1.0168x over previous
#include <cuda_runtime.h>
#include <cuda_bf16.h>
#include <cstdint>

#define D 64
#define MAXN 100000
#define MAXE 1200000
#define NEG_SLOPE 0.2f
#define SCAN_BLK 1024
#define MAX_SCAN_BLOCKS 128
#define SCATTER_BLOCKS 1024

// ---------------- scratch (static device globals; no allocation) ----------------
__device__ float g_z[MAXN * D];       // z = xW^T + b
__device__ float g_wt[D * D];         // W transposed
__device__ int   g_cnt[MAXN];         // in-degree histogram
__device__ int   g_off[MAXN + 1];     // CSR offsets
__device__ int   g_cur[MAXN];         // scatter cursors
__device__ int   g_csr[MAXE];         // src ids grouped by dst
__device__ int   g_bagg[MAX_SCAN_BLOCKS]; // lookback: 0=not ready, else block_agg+1

// ---------------- prep: zero histogram + lookback flags, transpose W ----------------
__global__ void prep_kernel(const float* __restrict__ W, int N) {
    int i = blockIdx.x * blockDim.x + threadIdx.x;
    if (i < N) g_cnt[i] = 0;
    if (i < MAX_SCAN_BLOCKS) g_bagg[i] = 0;
    if (i < D * D) {
        int j = i >> 6, k = i & 63;
        g_wt[k * D + j] = W[i];
    }
}

// ---------------- histogram of dst ----------------
__global__ __launch_bounds__(256) void hist_kernel(const int* __restrict__ ei, int E) {
    int e = blockIdx.x * blockDim.x + threadIdx.x;
    if (e < E) atomicAdd(&g_cnt[__ldg(ei + E + e)], 1);
}

// ---------------- single-pass scan with decoupled lookback ----------------
// nb <= 98 blocks, all co-resident on a 148-SM chip -> spin-wait is safe.
// Publishes block aggregate immediately (before lookback), so no circular wait.
__global__ __launch_bounds__(256) void scan_kernel(int N, int nb) {
    __shared__ int wsum[8];
    __shared__ int wpart[8];
    __shared__ int s_base;

    int t = threadIdx.x, blk = blockIdx.x;
    int wid = t >> 5, ln = t & 31;
    int i0 = blk * SCAN_BLK + t * 4;

    int c[4];
    #pragma unroll
    for (int j = 0; j < 4; j++) c[j] = (i0 + j < N) ? g_cnt[i0 + j] : 0;
    int tsum = c[0] + c[1] + c[2] + c[3];

    // warp-inclusive scan of tsum
    int v = tsum;
    #pragma unroll
    for (int off = 1; off < 32; off <<= 1) {
        int u = __shfl_up_sync(0xffffffffu, v, off);
        if (ln >= off) v += u;
    }
    if (ln == 31) wsum[wid] = v;
    __syncthreads();
    if (wid == 0) {
        int w = (ln < 8) ? wsum[ln] : 0;
        #pragma unroll
        for (int off = 1; off < 8; off <<= 1) {
            int u = __shfl_up_sync(0xffffffffu, w, off);
            if (ln >= off) w += u;
        }
        if (ln < 8) wsum[ln] = w;
    }
    __syncthreads();
    int wbase = (wid > 0) ? wsum[wid - 1] : 0;
    int excl = wbase + v - tsum;      // exclusive prefix within block
    int tot = wsum[7];                // block aggregate

    // publish aggregate (flag and data are the same word -> no fence needed)
    if (t == 0) atomicExch(&g_bagg[blk], tot + 1);

    // lookback: sum aggregates of all predecessor blocks
    int part = 0;
    for (int i = t; i < blk; i += 256) {
        int a;
        while ((a = *(volatile int*)&g_bagg[i]) == 0) { }
        part += a - 1;
    }
    #pragma unroll
    for (int off = 16; off > 0; off >>= 1)
        part += __shfl_xor_sync(0xffffffffu, part, off);
    if (ln == 0) wpart[wid] = part;
    __syncthreads();
    if (t == 0) {
        int bsum = 0;
        #pragma unroll
        for (int i = 0; i < 8; i++) bsum += wpart[i];
        s_base = bsum;
    }
    __syncthreads();
    int base = s_base;

    int run = base + excl;
    #pragma unroll
    for (int j = 0; j < 4; j++) {
        int idx = i0 + j;
        if (idx < N) g_cur[idx] = run;     // final g_off[idx]
        run += c[j];
        if (idx < N) g_off[idx + 1] = run;
    }
    if (blk == 0 && t == 0) g_off[0] = 0;
}

// ---------------- fused: z = xW^T + b (tile blocks) + CSR scatter (tail blocks) ----------------
// gemm is FMA/smem-bound; scatter is L2-atomic/scattered-write-bound -> disjoint pipes.
__global__ __launch_bounds__(256) void gemm_scatter_kernel(const float* __restrict__ x,
                                                           const float* __restrict__ b,
                                                           const int* __restrict__ ei,
                                                           int N, int E, int gemmBlocks) {
    __shared__ float Ws[D * D];
    __shared__ float Xs[64 * D];

    int tid = threadIdx.x;

    if (blockIdx.x >= gemmBlocks) {
        // -------- scatter path (grid-stride) --------
        int e0 = (blockIdx.x - gemmBlocks) * 256 + tid;
        for (int e = e0; e < E; e += SCATTER_BLOCKS * 256) {
            int src = __ldg(ei + e);
            int dst = __ldg(ei + E + e);
            int p = atomicAdd(&g_cur[dst], 1);
            g_csr[p] = src;
        }
        return;
    }

    // -------- GEMM path --------
    int row0 = blockIdx.x * 64;

    #pragma unroll
    for (int p = tid; p < D * D; p += 256) Ws[p] = g_wt[p];
    #pragma unroll
    for (int p = tid; p < 64 * D; p += 256) {
        int r = p >> 6, k = p & 63;
        int gr = row0 + r;
        Xs[p] = (gr < N) ? x[gr * D + k] : 0.0f;
    }
    __syncthreads();

    int tx = tid & 15;
    int ty = tid >> 4;

    float acc[4][4];
    #pragma unroll
    for (int r = 0; r < 4; r++)
        #pragma unroll
        for (int c = 0; c < 4; c++) acc[r][c] = 0.0f;

    #pragma unroll 8
    for (int k = 0; k < D; k++) {
        float4 w = *(const float4*)&Ws[k * D + tx * 4];
        #pragma unroll
        for (int r = 0; r < 4; r++) {
            float xv = Xs[(ty * 4 + r) * D + k];
            acc[r][0] = fmaf(xv, w.x, acc[r][0]);
            acc[r][1] = fmaf(xv, w.y, acc[r][1]);
            acc[r][2] = fmaf(xv, w.z, acc[r][2]);
            acc[r][3] = fmaf(xv, w.w, acc[r][3]);
        }
    }

    float4 bb = __ldg((const float4*)b + tx);
    #pragma unroll
    for (int r = 0; r < 4; r++) {
        int gr = row0 + ty * 4 + r;
        if (gr < N) {
            float4 o = make_float4(acc[r][0] + bb.x, acc[r][1] + bb.y,
                                   acc[r][2] + bb.z, acc[r][3] + bb.w);
            *(float4*)&g_z[gr * D + tx * 4] = o;
        }
    }
}

// ---------------- FUSED aggregate: one warp per dst, 8 lanes/edge, 8 edges/iter ----------------
__global__ __launch_bounds__(256, 3) void aggregate_kernel(const float* __restrict__ x,
                                                           const float* __restrict__ att,
                                                           float* __restrict__ out,
                                                           int N) {
    int dst = blockIdx.x * 8 + (threadIdx.x >> 5);
    if (dst >= N) return;
    int lane = threadIdx.x & 31;
    int q   = lane >> 3;
    int sub = lane & 7;

    const float4* zrd = (const float4*)(g_z + (dst << 6));
    float4 zd0 = zrd[sub], zd1 = zrd[sub + 8];
    float4 a0 = __ldg((const float4*)att + sub);
    float4 a1 = __ldg((const float4*)att + sub + 8);

    int beg = __ldg(&g_off[dst]);
    int end = __ldg(&g_off[dst + 1]);

    float4 acc0 = make_float4(0.f, 0.f, 0.f, 0.f);
    float4 acc1 = make_float4(0.f, 0.f, 0.f, 0.f);
    float s = 0.f;

    for (int k8 = beg; k8 < end; k8 += 8) {
        int kA = k8 + q;
        int kB = k8 + 4 + q;
        bool vA = (kA < end), vB = (kB < end);
        int sA = vA ? __ldg(&g_csr[kA]) : 0;
        int sB = vB ? __ldg(&g_csr[kB]) : 0;

        // issue all 12 row loads before any dependent math
        const float4* zrA = (const float4*)(g_z + (sA << 6));
        const float4* zrB = (const float4*)(g_z + (sB << 6));
        const float4* xrA = (const float4*)(x + (sA << 6));
        const float4* xrB = (const float4*)(x + (sB << 6));
        float4 zA0 = zrA[sub], zA1 = zrA[sub + 8];
        float4 zB0 = zrB[sub], zB1 = zrB[sub + 8];
        float4 xA0 = __ldg(xrA + sub), xA1 = __ldg(xrA + sub + 8);
        float4 xB0 = __ldg(xrB + sub), xB1 = __ldg(xrB + sub + 8);

        float u, pvA = 0.f, pvB = 0.f;
        u = zA0.x + zd0.x; u = (u > 0.f) ? u : NEG_SLOPE * u; pvA = fmaf(a0.x, u, pvA);
        u = zA0.y + zd0.y; u = (u > 0.f) ? u : NEG_SLOPE * u; pvA = fmaf(a0.y, u, pvA);
        u = zA0.z + zd0.z; u = (u > 0.f) ? u : NEG_SLOPE * u; pvA = fmaf(a0.z, u, pvA);
        u = zA0.w + zd0.w; u = (u > 0.f) ? u : NEG_SLOPE * u; pvA = fmaf(a0.w, u, pvA);
        u = zA1.x + zd1.x; u = (u > 0.f) ? u : NEG_SLOPE * u; pvA = fmaf(a1.x, u, pvA);
        u = zA1.y + zd1.y; u = (u > 0.f) ? u : NEG_SLOPE * u; pvA = fmaf(a1.y, u, pvA);
        u = zA1.z + zd1.z; u = (u > 0.f) ? u : NEG_SLOPE * u; pvA = fmaf(a1.z, u, pvA);
        u = zA1.w + zd1.w; u = (u > 0.f) ? u : NEG_SLOPE * u; pvA = fmaf(a1.w, u, pvA);

        u = zB0.x + zd0.x; u = (u > 0.f) ? u : NEG_SLOPE * u; pvB = fmaf(a0.x, u, pvB);
        u = zB0.y + zd0.y; u = (u > 0.f) ? u : NEG_SLOPE * u; pvB = fmaf(a0.y, u, pvB);
        u = zB0.z + zd0.z; u = (u > 0.f) ? u : NEG_SLOPE * u; pvB = fmaf(a0.z, u, pvB);
        u = zB0.w + zd0.w; u = (u > 0.f) ? u : NEG_SLOPE * u; pvB = fmaf(a0.w, u, pvB);
        u = zB1.x + zd1.x; u = (u > 0.f) ? u : NEG_SLOPE * u; pvB = fmaf(a1.x, u, pvB);
        u = zB1.y + zd1.y; u = (u > 0.f) ? u : NEG_SLOPE * u; pvB = fmaf(a1.y, u, pvB);
        u = zB1.z + zd1.z; u = (u > 0.f) ? u : NEG_SLOPE * u; pvB = fmaf(a1.z, u, pvB);
        u = zB1.w + zd1.w; u = (u > 0.f) ? u : NEG_SLOPE * u; pvB = fmaf(a1.w, u, pvB);

        #pragma unroll
        for (int off = 4; off > 0; off >>= 1) {
            pvA += __shfl_xor_sync(0xffffffffu, pvA, off);
            pvB += __shfl_xor_sync(0xffffffffu, pvB, off);
        }

        float exA = vA ? __expf(pvA) : 0.f;
        float exB = vB ? __expf(pvB) : 0.f;

        acc0.x = fmaf(exA, xA0.x, fmaf(exB, xB0.x, acc0.x));
        acc0.y = fmaf(exA, xA0.y, fmaf(exB, xB0.y, acc0.y));
        acc0.z = fmaf(exA, xA0.z, fmaf(exB, xB0.z, acc0.z));
        acc0.w = fmaf(exA, xA0.w, fmaf(exB, xB0.w, acc0.w));
        acc1.x = fmaf(exA, xA1.x, fmaf(exB, xB1.x, acc1.x));
        acc1.y = fmaf(exA, xA1.y, fmaf(exB, xB1.y, acc1.y));
        acc1.z = fmaf(exA, xA1.z, fmaf(exB, xB1.z, acc1.z));
        acc1.w = fmaf(exA, xA1.w, fmaf(exB, xB1.w, acc1.w));
        s += exA + exB;
    }

    // combine the 4 quarters
    #pragma unroll
    for (int off = 8; off <= 16; off <<= 1) {
        acc0.x += __shfl_xor_sync(0xffffffffu, acc0.x, off);
        acc0.y += __shfl_xor_sync(0xffffffffu, acc0.y, off);
        acc0.z += __shfl_xor_sync(0xffffffffu, acc0.z, off);
        acc0.w += __shfl_xor_sync(0xffffffffu, acc0.w, off);
        acc1.x += __shfl_xor_sync(0xffffffffu, acc1.x, off);
        acc1.y += __shfl_xor_sync(0xffffffffu, acc1.y, off);
        acc1.z += __shfl_xor_sync(0xffffffffu, acc1.z, off);
        acc1.w += __shfl_xor_sync(0xffffffffu, acc1.w, off);
        s      += __shfl_xor_sync(0xffffffffu, s, off);
    }

    float inv = (s > 0.f) ? __frcp_rn(s) : 0.f;
    if (q == 0) {
        float4* o = (float4*)(out + (dst << 6));
        o[sub]     = make_float4(acc0.x * inv, acc0.y * inv, acc0.z * inv, acc0.w * inv);
        o[sub + 8] = make_float4(acc1.x * inv, acc1.y * inv, acc1.z * inv, acc1.w * inv);
    }
}

// ---------------- launch ----------------
extern "C" void kernel_launch(void* const* d_in, const int* in_sizes, int n_in,
                              void* d_out, int out_size) {
    const float* x   = (const float*)d_in[0];
    const int*   ei  = (const int*)d_in[1];
    const float* W   = (const float*)d_in[2];
    const float* b   = (const float*)d_in[3];
    const float* att = (const float*)d_in[4];
    float* out = (float*)d_out;

    int N = in_sizes[0] / D;
    int E = in_sizes[1] / 2;
    int nb = (N + SCAN_BLK - 1) / SCAN_BLK;
    int gemmBlocks = (N + 63) / 64;

    prep_kernel<<<(N + 255) / 256, 256>>>(W, N);
    hist_kernel<<<(E + 255) / 256, 256>>>(ei, E);
    scan_kernel<<<nb, 256>>>(N, nb);
    gemm_scatter_kernel<<<gemmBlocks + SCATTER_BLOCKS, 256>>>(x, b, ei, N, E, gemmBlocks);
    aggregate_kernel<<<(N + 7) / 8, 256>>>(x, att, out, N);
}

// round 17
// speedup vs baseline: 1.0544x; 1.0250x over previous
#include <cuda_runtime.h>
#include <cuda_bf16.h>
#include <cstdint>

#define D 64
#define MAXN 100000
#define MAXE 1200000
#define NEG_SLOPE 0.2f
#define NB 444            // 3 blocks/SM x 148 SMs: guaranteed co-resident
#define NT 256
// NOTE: scan phase requires N <= NB*NT = 113664 (holds: N = 100000)

// ---------------- scratch (static device globals; no allocation) ----------------
__device__ float g_z[MAXN * D];
__device__ float g_wt[D * D];
__device__ int   g_cnt[MAXN];
__device__ int   g_off[MAXN + 1];
__device__ int   g_cur[MAXN];
__device__ int   g_csr[MAXE];
__device__ int   g_tot[NB];
__device__ volatile unsigned g_gen = 0;
__device__ unsigned g_count = 0;

// ---------------- grid-wide barrier (all NB blocks co-resident) ----------------
__device__ __forceinline__ void grid_sync() {
    __syncthreads();
    if (threadIdx.x == 0) {
        __threadfence();
        unsigned my = g_gen;
        if (atomicAdd(&g_count, 1u) == (unsigned)(NB - 1)) {
            atomicExch(&g_count, 0u);
            __threadfence();
            g_gen = my + 1;
        } else {
            while (g_gen == my) { }
        }
        __threadfence();
    }
    __syncthreads();
}

__global__ __launch_bounds__(NT, 3) void mega_kernel(
    const float* __restrict__ x, const int* __restrict__ ei,
    const float* __restrict__ W, const float* __restrict__ bias,
    const float* __restrict__ att, float* __restrict__ out,
    int N, int E)
{
    __shared__ float Ws[D * D];     // 16 KB
    __shared__ float Xs[64 * D];    // 16 KB
    __shared__ int   ssc[16];
    __shared__ int   sbase;

    int tid = threadIdx.x, bid = blockIdx.x;
    int wid = tid >> 5, ln = tid & 31;

    // ===== P0: zero histogram + transpose W =====
    for (int i = bid * NT + tid; i < N; i += NB * NT) g_cnt[i] = 0;
    for (int i = bid * NT + tid; i < D * D; i += NB * NT) {
        int j = i >> 6, k = i & 63;
        g_wt[k * D + j] = W[i];
    }
    grid_sync();

    // ===== P1: histogram of dst =====
    for (int e = bid * NT + tid; e < E; e += NB * NT)
        atomicAdd(&g_cnt[__ldg(ei + E + e)], 1);
    grid_sync();

    // ===== P2: block-local scan (256 counts/block); c & incl stay in registers =====
    int i_sc = bid * NT + tid;
    int c = (i_sc < N) ? g_cnt[i_sc] : 0;
    {
        int v = c;
        #pragma unroll
        for (int off = 1; off < 32; off <<= 1) {
            int u = __shfl_up_sync(0xffffffffu, v, off);
            if (ln >= off) v += u;
        }
        if (ln == 31) ssc[wid] = v;
        __syncthreads();
        if (wid == 0) {
            int w = (ln < 8) ? ssc[ln] : 0;
            #pragma unroll
            for (int off = 1; off < 8; off <<= 1) {
                int u = __shfl_up_sync(0xffffffffu, w, off);
                if (ln >= off) w += u;
            }
            if (ln < 8) ssc[ln] = w;
        }
        __syncthreads();
        int wbase = (wid > 0) ? ssc[wid - 1] : 0;
        int incl = wbase + v;                 // block-local inclusive prefix
        if (tid == NT - 1) g_tot[bid] = incl; // block total
        grid_sync();

        // ===== P3: global base = sum of predecessor block totals; write off+cur =====
        int part = 0;
        for (int j = tid; j < bid; j += NT) part += g_tot[j];
        #pragma unroll
        for (int off = 16; off > 0; off >>= 1)
            part += __shfl_xor_sync(0xffffffffu, part, off);
        if (ln == 0) ssc[8 + wid] = part;
        __syncthreads();
        if (tid == 0) {
            int s = 0;
            #pragma unroll
            for (int k = 0; k < 8; k++) s += ssc[8 + k];
            sbase = s;
        }
        __syncthreads();
        if (i_sc < N) {
            int fin = sbase + incl;
            g_off[i_sc + 1] = fin;
            g_cur[i_sc] = fin - c;
        }
        if (bid == 0 && tid == 0) g_off[0] = 0;
    }
    grid_sync();

    // ===== P4: gemm (tile-strided) + scatter (edge-strided), interleaved order =====
    {
        int tiles = (N + 63) / 64;
        bool scatFirst = (bid & 1);

        for (int pass = 0; pass < 2; pass++) {
            bool doScat = (pass == 0) ? scatFirst : !scatFirst;
            if (doScat) {
                for (int e = bid * NT + tid; e < E; e += NB * NT) {
                    int src = __ldg(ei + e);
                    int dst = __ldg(ei + E + e);
                    int p = atomicAdd(&g_cur[dst], 1);
                    g_csr[p] = src;
                }
            } else {
                for (int p = tid; p < D * D; p += NT) Ws[p] = g_wt[p];
                for (int tile = bid; tile < tiles; tile += NB) {
                    int row0 = tile * 64;
                    __syncthreads();
                    for (int p = tid; p < 64 * D; p += NT) {
                        int r = p >> 6, k = p & 63;
                        int gr = row0 + r;
                        Xs[p] = (gr < N) ? x[gr * D + k] : 0.0f;
                    }
                    __syncthreads();

                    int tx = tid & 15, ty = tid >> 4;
                    float acc[4][4];
                    #pragma unroll
                    for (int r = 0; r < 4; r++)
                        #pragma unroll
                        for (int cc = 0; cc < 4; cc++) acc[r][cc] = 0.0f;

                    #pragma unroll 8
                    for (int k = 0; k < D; k++) {
                        float4 w = *(const float4*)&Ws[k * D + tx * 4];
                        #pragma unroll
                        for (int r = 0; r < 4; r++) {
                            float xv = Xs[(ty * 4 + r) * D + k];
                            acc[r][0] = fmaf(xv, w.x, acc[r][0]);
                            acc[r][1] = fmaf(xv, w.y, acc[r][1]);
                            acc[r][2] = fmaf(xv, w.z, acc[r][2]);
                            acc[r][3] = fmaf(xv, w.w, acc[r][3]);
                        }
                    }

                    float4 bb = __ldg((const float4*)bias + tx);
                    #pragma unroll
                    for (int r = 0; r < 4; r++) {
                        int gr = row0 + ty * 4 + r;
                        if (gr < N) {
                            float4 o = make_float4(acc[r][0] + bb.x, acc[r][1] + bb.y,
                                                   acc[r][2] + bb.z, acc[r][3] + bb.w);
                            *(float4*)&g_z[gr * D + tx * 4] = o;
                        }
                    }
                }
            }
        }
    }
    grid_sync();

    // ===== P5: aggregate — warp per dst, 8 lanes/edge, 8 edges/iter =====
    {
        int lane = tid & 31;
        int q = lane >> 3;
        int sub = lane & 7;
        float4 a0 = __ldg((const float4*)att + sub);
        float4 a1 = __ldg((const float4*)att + sub + 8);

        for (int dst = bid * 8 + wid; dst < N; dst += NB * 8) {
            const float4* zrd = (const float4*)(g_z + (dst << 6));
            float4 zd0 = zrd[sub], zd1 = zrd[sub + 8];

            int beg = __ldg(&g_off[dst]);
            int end = __ldg(&g_off[dst + 1]);

            float4 acc0 = make_float4(0.f, 0.f, 0.f, 0.f);
            float4 acc1 = make_float4(0.f, 0.f, 0.f, 0.f);
            float s = 0.f;

            for (int k8 = beg; k8 < end; k8 += 8) {
                int kA = k8 + q;
                int kB = k8 + 4 + q;
                bool vA = (kA < end), vB = (kB < end);
                int sA = vA ? __ldg(&g_csr[kA]) : 0;
                int sB = vB ? __ldg(&g_csr[kB]) : 0;

                const float4* zrA = (const float4*)(g_z + (sA << 6));
                const float4* zrB = (const float4*)(g_z + (sB << 6));
                const float4* xrA = (const float4*)(x + (sA << 6));
                const float4* xrB = (const float4*)(x + (sB << 6));
                float4 zA0 = zrA[sub], zA1 = zrA[sub + 8];
                float4 zB0 = zrB[sub], zB1 = zrB[sub + 8];
                float4 xA0 = __ldg(xrA + sub), xA1 = __ldg(xrA + sub + 8);
                float4 xB0 = __ldg(xrB + sub), xB1 = __ldg(xrB + sub + 8);

                float u, pvA = 0.f, pvB = 0.f;
                u = zA0.x + zd0.x; u = (u > 0.f) ? u : NEG_SLOPE * u; pvA = fmaf(a0.x, u, pvA);
                u = zA0.y + zd0.y; u = (u > 0.f) ? u : NEG_SLOPE * u; pvA = fmaf(a0.y, u, pvA);
                u = zA0.z + zd0.z; u = (u > 0.f) ? u : NEG_SLOPE * u; pvA = fmaf(a0.z, u, pvA);
                u = zA0.w + zd0.w; u = (u > 0.f) ? u : NEG_SLOPE * u; pvA = fmaf(a0.w, u, pvA);
                u = zA1.x + zd1.x; u = (u > 0.f) ? u : NEG_SLOPE * u; pvA = fmaf(a1.x, u, pvA);
                u = zA1.y + zd1.y; u = (u > 0.f) ? u : NEG_SLOPE * u; pvA = fmaf(a1.y, u, pvA);
                u = zA1.z + zd1.z; u = (u > 0.f) ? u : NEG_SLOPE * u; pvA = fmaf(a1.z, u, pvA);
                u = zA1.w + zd1.w; u = (u > 0.f) ? u : NEG_SLOPE * u; pvA = fmaf(a1.w, u, pvA);

                u = zB0.x + zd0.x; u = (u > 0.f) ? u : NEG_SLOPE * u; pvB = fmaf(a0.x, u, pvB);
                u = zB0.y + zd0.y; u = (u > 0.f) ? u : NEG_SLOPE * u; pvB = fmaf(a0.y, u, pvB);
                u = zB0.z + zd0.z; u = (u > 0.f) ? u : NEG_SLOPE * u; pvB = fmaf(a0.z, u, pvB);
                u = zB0.w + zd0.w; u = (u > 0.f) ? u : NEG_SLOPE * u; pvB = fmaf(a0.w, u, pvB);
                u = zB1.x + zd1.x; u = (u > 0.f) ? u : NEG_SLOPE * u; pvB = fmaf(a1.x, u, pvB);
                u = zB1.y + zd1.y; u = (u > 0.f) ? u : NEG_SLOPE * u; pvB = fmaf(a1.y, u, pvB);
                u = zB1.z + zd1.z; u = (u > 0.f) ? u : NEG_SLOPE * u; pvB = fmaf(a1.z, u, pvB);
                u = zB1.w + zd1.w; u = (u > 0.f) ? u : NEG_SLOPE * u; pvB = fmaf(a1.w, u, pvB);

                #pragma unroll
                for (int off = 4; off > 0; off >>= 1) {
                    pvA += __shfl_xor_sync(0xffffffffu, pvA, off);
                    pvB += __shfl_xor_sync(0xffffffffu, pvB, off);
                }

                float exA = vA ? __expf(pvA) : 0.f;
                float exB = vB ? __expf(pvB) : 0.f;

                acc0.x = fmaf(exA, xA0.x, fmaf(exB, xB0.x, acc0.x));
                acc0.y = fmaf(exA, xA0.y, fmaf(exB, xB0.y, acc0.y));
                acc0.z = fmaf(exA, xA0.z, fmaf(exB, xB0.z, acc0.z));
                acc0.w = fmaf(exA, xA0.w, fmaf(exB, xB0.w, acc0.w));
                acc1.x = fmaf(exA, xA1.x, fmaf(exB, xB1.x, acc1.x));
                acc1.y = fmaf(exA, xA1.y, fmaf(exB, xB1.y, acc1.y));
                acc1.z = fmaf(exA, xA1.z, fmaf(exB, xB1.z, acc1.z));
                acc1.w = fmaf(exA, xA1.w, fmaf(exB, xB1.w, acc1.w));
                s += exA + exB;
            }

            #pragma unroll
            for (int off = 8; off <= 16; off <<= 1) {
                acc0.x += __shfl_xor_sync(0xffffffffu, acc0.x, off);
                acc0.y += __shfl_xor_sync(0xffffffffu, acc0.y, off);
                acc0.z += __shfl_xor_sync(0xffffffffu, acc0.z, off);
                acc0.w += __shfl_xor_sync(0xffffffffu, acc0.w, off);
                acc1.x += __shfl_xor_sync(0xffffffffu, acc1.x, off);
                acc1.y += __shfl_xor_sync(0xffffffffu, acc1.y, off);
                acc1.z += __shfl_xor_sync(0xffffffffu, acc1.z, off);
                acc1.w += __shfl_xor_sync(0xffffffffu, acc1.w, off);
                s      += __shfl_xor_sync(0xffffffffu, s, off);
            }

            float inv = (s > 0.f) ? __frcp_rn(s) : 0.f;
            if (q == 0) {
                float4* o = (float4*)(out + (dst << 6));
                o[sub]     = make_float4(acc0.x * inv, acc0.y * inv, acc0.z * inv, acc0.w * inv);
                o[sub + 8] = make_float4(acc1.x * inv, acc1.y * inv, acc1.z * inv, acc1.w * inv);
            }
        }
    }
}

// ---------------- launch ----------------
extern "C" void kernel_launch(void* const* d_in, const int* in_sizes, int n_in,
                              void* d_out, int out_size) {
    const float* x   = (const float*)d_in[0];
    const int*   ei  = (const int*)d_in[1];
    const float* W   = (const float*)d_in[2];
    const float* b   = (const float*)d_in[3];
    const float* att = (const float*)d_in[4];
    float* out = (float*)d_out;

    int N = in_sizes[0] / D;
    int E = in_sizes[1] / 2;

    mega_kernel<<<NB, NT>>>(x, ei, W, b, att, out, N, E);
}